// round 8
// baseline (speedup 1.0000x reference)
#include <cuda_runtime.h>
#include <cuda_fp16.h>
#include <math.h>
#include <stdint.h>

#define NNODES 10000
#define NEDGES 64000
#define IN_DIM 1247
#define KPAD   1280          /* IN_DIM padded to 40 k-tiles */
#define NKT0   40            /* KPAD/32 */
#define NKT1   32            /* 1024/32 */
#define NRT    79            /* ceil(10000/128) row tiles */
#define MPAD   (NRT * 128)   /* 10112 */
#define NH 4
#define DD0 256
#define DD1 8
#define OUTD 6
#define HD0 1024
#define HD1 32
#define NBIG 3104            /* 1024*3 + 32 (z2) */
#define NCT0 25              /* ceil(3104/128) col tiles */
#define L1W 96

// ------------------- scratch (device globals) --------------------------------
__device__ __align__(16) float  g_colsum[IN_DIM];
__device__ __align__(16) __half g_hA[(size_t)NRT * NKT0 * 4096];
__device__ __align__(16) __half g_WbigT[(size_t)NCT0 * NKT0 * 4096];
__device__ __align__(16) __half g_WcatT[(size_t)1 * NKT1 * 4096];
__device__ __align__(16) float  g_big[(size_t)NNODES * NBIG];   /* fs0|fd0|res0|z2 */
__device__ __align__(16) __half g_x1A[(size_t)NRT * NKT1 * 4096];
__device__ __align__(16) float  g_l1out[(size_t)NNODES * L1W];
__device__ __align__(16) float  g_h3[NNODES * HD1];
__device__ __align__(16) float  g_out1[NNODES * HD1];
__device__ float g_es2[NNODES * NH];
__device__ float g_ed2[NNODES * NH];
__device__ float g_lg0[NEDGES * NH];
__device__ float g_lg1[NEDGES * NH];
__device__ float g_lg2[NEDGES * NH];
__device__ int   g_deg[NNODES];
__device__ int   g_fill[NNODES];
__device__ int   g_csr_off[NNODES + 1];
__device__ int   g_csr_edge[NEDGES];

__device__ __forceinline__ float lrelu(float x) { return x > 0.f ? x : 0.2f * x; }
// permuted position of col k (0..31) within a 32-half row:
// lane tg gets its 8 needed halves (both 8-col groups, both k-steps) contiguous.
__device__ __forceinline__ int permH(int k) {
    return (((k >> 1) & 3) << 3) | (((k >> 4) & 1) << 2) | (((k >> 3) & 1) << 1) | (k & 1);
}
__device__ __forceinline__ int tileOffH(int r, int k) { return (r << 5) + permH(k); }
__device__ __forceinline__ void cp16(uint32_t s, const void* g) {
    asm volatile("cp.async.cg.shared.global [%0], [%1], 16;" :: "r"(s), "l"(g));
}

// ------------------- preprocessing ------------------------------------------
__global__ void zeroKernel() {
    int i = blockIdx.x * 256 + threadIdx.x;
    if (i < IN_DIM) g_colsum[i] = 0.f;
    if (i < NNODES) { g_deg[i] = 0; g_fill[i] = 0; }
}

__global__ void colsumKernel(const float* __restrict__ f) {
    int j = blockIdx.x * 256 + threadIdx.x;
    if (j >= IN_DIM) return;
    float s = 0.f;
    for (int i = blockIdx.y; i < NNODES; i += gridDim.y)
        s += f[(size_t)i * IN_DIM + j];
    atomicAdd(&g_colsum[j], s);
}

__global__ void preprocessKernel(const float* __restrict__ f,
                                 const float* __restrict__ tm,
                                 const float* __restrict__ am,
                                 const float* __restrict__ vm) {
    __shared__ float sh[IN_DIM];
    __shared__ float red[8];
    int n = blockIdx.x;            // 0..MPAD-1
    int t = threadIdx.x;
    int r = n & 127, rt = n >> 7;
    __half* base = g_hA + ((size_t)rt * NKT0 << 12);
    if (n >= NNODES) {
        for (int j = t; j < KPAD; j += 256)
            base[((j >> 5) << 12) + tileOffH(r, j & 31)] = __float2half(0.f);
        return;
    }
    const float* row = f + (size_t)n * IN_DIM;
    const float invN = 1.f / (float)NNODES;
    float s = 0.f;
    for (int j = t; j < IN_DIM; j += 256) {
        float v = row[j];
        v = (v == 0.f) ? (0.5f * g_colsum[j] * invN) : v;
        sh[j] = v;
        s += fabsf(v);
    }
    for (int off = 16; off; off >>= 1) s += __shfl_down_sync(0xffffffffu, s, off);
    if ((t & 31) == 0) red[t >> 5] = s;
    __syncthreads();
    if (t == 0) {
        float tot = 0.f;
        for (int w = 0; w < 8; w++) tot += red[w];
        red[0] = 1.f / fmaxf(tot, 1e-12f);
    }
    __syncthreads();
    float inv = red[0];
    for (int j = t; j < KPAD; j += 256) {
        float v = 0.f;
        if (j < IN_DIM) v = sh[j] * inv * (tm[j] + am[j] + vm[j]);
        base[((j >> 5) << 12) + tileOffH(r, j & 31)] = __float2half(v);
    }
}

// g_WbigT: cols [Wl0|Wr0|Wres0|W2packed|0], fp16 packed-tile images
__global__ void packWbigTKernel(const float* __restrict__ Wl0,
                                const float* __restrict__ Wr0,
                                const float* __restrict__ Wres0,
                                const float* __restrict__ W2) {
    int i = blockIdx.x * 256 + threadIdx.x;
    if (i >= NCT0 * NKT0 * 4096) return;
    int ct = i / (NKT0 * 4096);
    int rem = i % (NKT0 * 4096);
    int kt = rem >> 12;
    int p = rem & 4095;
    int r = p >> 5, pos = p & 31;
    // invert permH
    int tg = (pos >> 3) & 3, s = (pos >> 2) & 1, hi = (pos >> 1) & 1, lo = pos & 1;
    int kl = 16 * s + 8 * hi + 2 * tg + lo;
    int k = kt * 32 + kl;
    int n = ct * 128 + r;
    float v = 0.f;
    if (k < IN_DIM) {
        if (n < HD0) v = Wl0[(size_t)k * HD0 + n];
        else if (n < 2 * HD0) v = Wr0[(size_t)k * HD0 + (n - HD0)];
        else if (n < 3 * HD0) v = Wres0[(size_t)k * HD0 + (n - 2 * HD0)];
        else if (n < 3 * HD0 + HD1) {
            int cc = n - 3 * HD0;
            v = W2[((size_t)(cc >> 3) * IN_DIM + k) * DD1 + (cc & 7)];
        }
    }
    g_WbigT[i] = __float2half(v);
}

// g_WcatT: cols [Wl1|Wr1|Wres1|0], K=1024, fp16
__global__ void packWcatTKernel(const float* __restrict__ Wl1,
                                const float* __restrict__ Wr1,
                                const float* __restrict__ Wres1) {
    int i = blockIdx.x * 256 + threadIdx.x;
    if (i >= NKT1 * 4096) return;
    int kt = i >> 12;
    int p = i & 4095;
    int r = p >> 5, pos = p & 31;
    int tg = (pos >> 3) & 3, s = (pos >> 2) & 1, hi = (pos >> 1) & 1, lo = pos & 1;
    int kl = 16 * s + 8 * hi + 2 * tg + lo;
    int k = kt * 32 + kl;
    int n = r;
    float v = 0.f;
    if (n < HD1) v = Wl1[(size_t)k * HD1 + n];
    else if (n < 2 * HD1) v = Wr1[(size_t)k * HD1 + (n - HD1)];
    else if (n < L1W) v = Wres1[(size_t)k * HD1 + (n - 2 * HD1)];
    g_WcatT[i] = __float2half(v);
}

// ------------------- CSR build ----------------------------------------------
__global__ void histKernel(const int* __restrict__ dst) {
    int e = blockIdx.x * 256 + threadIdx.x;
    if (e < NEDGES) atomicAdd(&g_deg[dst[e]], 1);
}

__global__ void scanKernel() {
    __shared__ int sums[1024];
    const int CH = (NNODES + 1023) / 1024;
    int t = threadIdx.x;
    int base = t * CH;
    int local[CH];
    int s = 0;
    for (int i = 0; i < CH; i++) {
        int v = (base + i < NNODES) ? g_deg[base + i] : 0;
        local[i] = s;
        s += v;
    }
    sums[t] = s;
    __syncthreads();
    for (int off = 1; off < 1024; off <<= 1) {
        int v = (t >= off) ? sums[t - off] : 0;
        __syncthreads();
        sums[t] += v;
        __syncthreads();
    }
    int excl = (t == 0) ? 0 : sums[t - 1];
    for (int i = 0; i < CH; i++)
        if (base + i < NNODES) g_csr_off[base + i] = excl + local[i];
    if (t == 1023) g_csr_off[NNODES] = sums[1023];
}

__global__ void fillCsrKernel(const int* __restrict__ dst) {
    int e = blockIdx.x * 256 + threadIdx.x;
    if (e >= NEDGES) return;
    int d = dst[e];
    int pos = atomicAdd(&g_fill[d], 1);
    g_csr_edge[g_csr_off[d] + pos] = e;
}

// ------------------- fp16 tensor GEMM on pre-packed tiles --------------------
// Apack/Bpack: [tile][nKt][4096] __half tiles (128 rows x 32 halves, permH).
// C row-major fp32. Block 128x128x32, 8 warps (2m x 4n), warp tile 64x32.
// mma.sync.m16n8k16.f32.f16.f16.f32, double-buffered cp.async.
#define GEMM_SMEM 32768

__global__ __launch_bounds__(256, 2) void fp16GemmKernel(
    const __half* __restrict__ Apack, const __half* __restrict__ Bpack,
    int nKt, float* __restrict__ C, int ldc, int Mrows, int Ncols) {
    extern __shared__ __align__(16) char smraw[];
    __half* sm = (__half*)smraw;
    int tid = threadIdx.x;
    int lane = tid & 31;
    int w = tid >> 5;
    int wm = w & 1, wn = w >> 1;
    int g = lane >> 2, tg = lane & 3;
    int r0 = blockIdx.x * 128, c0 = blockIdx.y * 128;

    const __half* gA = Apack + ((size_t)blockIdx.x * nKt << 12);
    const __half* gB = Bpack + ((size_t)blockIdx.y * nKt << 12);
    uint32_t sbase = (uint32_t)__cvta_generic_to_shared(sm);
    // buffer b: A at sbase + b*16384, B at +8192
    float acc[4][4][4];
#pragma unroll
    for (int i = 0; i < 4; i++)
#pragma unroll
        for (int j = 0; j < 4; j++)
#pragma unroll
            for (int r = 0; r < 4; r++) acc[i][j][r] = 0.f;

    // prologue: tile 0 -> buf 0 (A 8KB + B 8KB; 64B per thread)
#pragma unroll
    for (int q = 0; q < 4; q++) {
        int ci = tid * 4 + q;             // 16B chunk id, 0..1023
        const __half* src = (ci < 512) ? (gA + ci * 8) : (gB + (ci - 512) * 8);
        cp16(sbase + ci * 16, src);
    }
    asm volatile("cp.async.commit_group;" ::: "memory");

    for (int kt = 0; kt < nKt; kt++) {
        int buf = kt & 1;
        bool hasNext = (kt + 1) < nKt;
        if (hasNext) {
            const __half* nA = gA + ((size_t)(kt + 1) << 12);
            const __half* nB = gB + ((size_t)(kt + 1) << 12);
            uint32_t nb = sbase + (buf ^ 1) * 16384u;
#pragma unroll
            for (int q = 0; q < 4; q++) {
                int ci = tid * 4 + q;
                const __half* src = (ci < 512) ? (nA + ci * 8) : (nB + (ci - 512) * 8);
                cp16(nb + ci * 16, src);
            }
            asm volatile("cp.async.commit_group;" ::: "memory");
            asm volatile("cp.async.wait_group 1;" ::: "memory");
        } else {
            asm volatile("cp.async.wait_group 0;" ::: "memory");
        }
        __syncthreads();

        const __half* As = sm + buf * 8192;
        const __half* Bs = sm + 4096 + buf * 8192;
        uint4 Af0[4], Af1[4], Bf[4];
#pragma unroll
        for (int mf = 0; mf < 4; mf++) {
            int r = wm * 64 + mf * 16 + g;
            Af0[mf] = *(const uint4*)(As + (r << 5) + (tg << 3));
            Af1[mf] = *(const uint4*)(As + ((r + 8) << 5) + (tg << 3));
        }
#pragma unroll
        for (int nf = 0; nf < 4; nf++) {
            int cc = wn * 32 + nf * 8 + g;
            Bf[nf] = *(const uint4*)(Bs + (cc << 5) + (tg << 3));
        }
#pragma unroll
        for (int s = 0; s < 2; s++) {
#pragma unroll
            for (int mf = 0; mf < 4; mf++) {
                uint32_t a0 = s ? Af0[mf].z : Af0[mf].x;
                uint32_t a1 = s ? Af1[mf].z : Af1[mf].x;
                uint32_t a2 = s ? Af0[mf].w : Af0[mf].y;
                uint32_t a3 = s ? Af1[mf].w : Af1[mf].y;
#pragma unroll
                for (int nf = 0; nf < 4; nf++) {
                    uint32_t b0 = s ? Bf[nf].z : Bf[nf].x;
                    uint32_t b1 = s ? Bf[nf].w : Bf[nf].y;
                    asm volatile(
                        "mma.sync.aligned.m16n8k16.row.col.f32.f16.f16.f32 "
                        "{%0,%1,%2,%3}, {%4,%5,%6,%7}, {%8,%9}, {%0,%1,%2,%3};"
                        : "+f"(acc[mf][nf][0]), "+f"(acc[mf][nf][1]),
                          "+f"(acc[mf][nf][2]), "+f"(acc[mf][nf][3])
                        : "r"(a0), "r"(a1), "r"(a2), "r"(a3),
                          "r"(b0), "r"(b1));
                }
            }
        }
        __syncthreads();
    }

    // epilogue
#pragma unroll
    for (int mf = 0; mf < 4; mf++) {
        int rA = r0 + wm * 64 + mf * 16 + g;
        int rB = rA + 8;
#pragma unroll
        for (int nf = 0; nf < 4; nf++) {
            int gc = c0 + wn * 32 + nf * 8 + tg * 2;
            if (gc < Ncols) {
                if (rA < Mrows) C[(size_t)rA * ldc + gc] = acc[mf][nf][0];
                if (rB < Mrows) C[(size_t)rB * ldc + gc] = acc[mf][nf][2];
            }
            if (gc + 1 < Ncols) {
                if (rA < Mrows) C[(size_t)rA * ldc + gc + 1] = acc[mf][nf][1];
                if (rB < Mrows) C[(size_t)rB * ldc + gc + 1] = acc[mf][nf][3];
            }
        }
    }
}

// ------------------- gat_inner (h3) ------------------------------------------
__global__ void innerNodeTermsKernel(const float* __restrict__ a2) {
    int idx = blockIdx.x * 256 + threadIdx.x;
    if (idx >= NNODES * NH) return;
    int n = idx / NH, h = idx % NH;
    const float* z = g_big + (size_t)n * NBIG + 3 * HD0 + h * DD1;
    float es = 0.f, ed = 0.f;
#pragma unroll
    for (int o = 0; o < DD1; o++) {
        es = fmaf(z[o], a2[h * 2 * DD1 + o], es);
        ed = fmaf(z[o], a2[h * 2 * DD1 + DD1 + o], ed);
    }
    g_es2[idx] = es;
    g_ed2[idx] = ed;
}

__global__ void innerEdgeLogitsKernel(const int* __restrict__ src,
                                      const int* __restrict__ dst) {
    int idx = blockIdx.x * 256 + threadIdx.x;
    if (idx >= NEDGES * NH) return;
    int e = idx / NH, h = idx % NH;
    g_lg2[idx] = lrelu(g_es2[src[e] * NH + h] + g_ed2[dst[e] * NH + h]);
}

__global__ void segSoftmaxKernel(float* __restrict__ lg) {
    int idx = blockIdx.x * 256 + threadIdx.x;
    if (idx >= NNODES * NH) return;
    int n = idx / NH, h = idx % NH;
    int s = g_csr_off[n], t = g_csr_off[n + 1];
    float m = -1e30f;
    for (int p = s; p < t; p++) m = fmaxf(m, lg[g_csr_edge[p] * NH + h]);
    float den = 0.f;
    for (int p = s; p < t; p++) {
        int a = g_csr_edge[p] * NH + h;
        float pv = __expf(lg[a] - m);
        den += pv;
        lg[a] = pv;
    }
    float inv = 1.f / fmaxf(den, 1e-9f);
    for (int p = s; p < t; p++) lg[g_csr_edge[p] * NH + h] *= inv;
}

__global__ void aggSmallKernel(const float* __restrict__ vals, int vstride,
                               const float* __restrict__ lg,
                               const int* __restrict__ src,
                               const float* __restrict__ res, int rstride,
                               const float* __restrict__ bias,
                               float* __restrict__ out, int doRelu) {
    int w = (blockIdx.x * blockDim.x + threadIdx.x) >> 5;
    int lane = threadIdx.x & 31;
    if (w >= NNODES) return;
    int h = lane >> 3;
    int s = g_csr_off[w], t = g_csr_off[w + 1];
    float acc = 0.f;
    for (int p = s; p < t; p++) {
        int e = g_csr_edge[p];
        acc = fmaf(lg[e * NH + h], vals[(size_t)src[e] * vstride + lane], acc);
    }
    if (res) acc += res[(size_t)w * rstride + lane] + bias[lane];
    if (doRelu) acc = fmaxf(acc, 0.f);
    out[w * HD1 + lane] = acc;
}

// ------------------- gatv2 layer 0 (D=256) ------------------------------------
__global__ void gatv2EdgeLogits0Kernel(const int* __restrict__ src,
                                       const int* __restrict__ dst,
                                       const float* __restrict__ a0) {
    int e = blockIdx.x;
    int t = threadIdx.x;  // 128
    const float4* fs = (const float4*)(g_big + (size_t)src[e] * NBIG);
    const float4* fd = (const float4*)(g_big + (size_t)dst[e] * NBIG + HD0);
    const float4* a4 = (const float4*)a0;
    float partial = 0.f;
#pragma unroll
    for (int q = 0; q < 2; q++) {
        int i4 = t * 2 + q;
        float4 u = fs[i4], v = fd[i4], w = a4[i4];
        partial = fmaf(lrelu(u.x + v.x), w.x, partial);
        partial = fmaf(lrelu(u.y + v.y), w.y, partial);
        partial = fmaf(lrelu(u.z + v.z), w.z, partial);
        partial = fmaf(lrelu(u.w + v.w), w.w, partial);
    }
    for (int off = 16; off; off >>= 1)
        partial += __shfl_down_sync(0xffffffffu, partial, off);
    if ((t & 31) == 0) g_lg0[e * NH + (t >> 5)] = partial;
}

// aggregate layer-0, residual+bias+relu; emit x1 as packed fp16 tiles
__global__ void gatv2Agg0Kernel(const int* __restrict__ src,
                                const float* __restrict__ b0) {
    int n = blockIdx.x;            // 0..MPAD-1
    int t = threadIdx.x;           // 256; 4 consecutive k each
    int r = n & 127, rt = n >> 7;
    __half* base = g_x1A + ((size_t)rt * NKT1 << 12);
    if (n >= NNODES) {
#pragma unroll
        for (int q = 0; q < 4; q++) {
            int k = t * 4 + q;
            base[((k >> 5) << 12) + tileOffH(r, k & 31)] = __float2half(0.f);
        }
        return;
    }
    int h = t >> 6;
    int s = g_csr_off[n], e1 = g_csr_off[n + 1];
    float4 acc = make_float4(0.f, 0.f, 0.f, 0.f);
    for (int p = s; p < e1; p++) {
        int e = g_csr_edge[p];
        float a = g_lg0[e * NH + h];
        float4 v = ((const float4*)(g_big + (size_t)src[e] * NBIG))[t];
        acc.x = fmaf(a, v.x, acc.x);
        acc.y = fmaf(a, v.y, acc.y);
        acc.z = fmaf(a, v.z, acc.z);
        acc.w = fmaf(a, v.w, acc.w);
    }
    float4 rr = ((const float4*)(g_big + (size_t)n * NBIG + 2 * HD0))[t];
    float4 bb = ((const float4*)b0)[t];
    float o[4];
    o[0] = fmaxf(acc.x + rr.x + bb.x, 0.f);
    o[1] = fmaxf(acc.y + rr.y + bb.y, 0.f);
    o[2] = fmaxf(acc.z + rr.z + bb.z, 0.f);
    o[3] = fmaxf(acc.w + rr.w + bb.w, 0.f);
#pragma unroll
    for (int q = 0; q < 4; q++) {
        int k = t * 4 + q;
        base[((k >> 5) << 12) + tileOffH(r, k & 31)] = __float2half(o[q]);
    }
}

// ------------------- gatv2 layer 1 (D=8) --------------------------------------
__global__ void gatv2EdgeLogits1Kernel(const int* __restrict__ src,
                                       const int* __restrict__ dst,
                                       const float* __restrict__ a1) {
    int w = (blockIdx.x * blockDim.x + threadIdx.x) >> 5;
    int lane = threadIdx.x & 31;
    if (w >= NEDGES) return;
    float x = g_l1out[(size_t)src[w] * L1W + lane] +
              g_l1out[(size_t)dst[w] * L1W + HD1 + lane];
    float p = lrelu(x) * a1[lane];
    p += __shfl_down_sync(0xffffffffu, p, 4, 8);
    p += __shfl_down_sync(0xffffffffu, p, 2, 8);
    p += __shfl_down_sync(0xffffffffu, p, 1, 8);
    if ((lane & 7) == 0) g_lg1[w * NH + (lane >> 3)] = p;
}

// ------------------- final linear ---------------------------------------------
__global__ void finalLinearKernel(const float* __restrict__ Wlin,
                                  const float* __restrict__ blin,
                                  float* __restrict__ out) {
    int n = blockIdx.x * 256 + threadIdx.x;
    if (n >= NNODES) return;
    float acc[OUTD];
#pragma unroll
    for (int c = 0; c < OUTD; c++) acc[c] = blin[c];
#pragma unroll 4
    for (int j = 0; j < HD1; j++) {
        float v = g_h3[n * HD1 + j];
#pragma unroll
        for (int c = 0; c < OUTD; c++) acc[c] = fmaf(v, Wlin[j * OUTD + c], acc[c]);
    }
#pragma unroll 4
    for (int j = 0; j < HD1; j++) {
        float v = g_out1[n * HD1 + j];
#pragma unroll
        for (int c = 0; c < OUTD; c++)
            acc[c] = fmaf(v, Wlin[(HD1 + j) * OUTD + c], acc[c]);
    }
#pragma unroll
    for (int c = 0; c < OUTD; c++) out[n * OUTD + c] = acc[c];
}

// ------------------- launch ---------------------------------------------------
extern "C" void kernel_launch(void* const* d_in, const int* in_sizes, int n_in,
                              void* d_out, int out_size) {
    const float* features = (const float*)d_in[0];
    const int* src = (const int*)d_in[1];
    const int* dst = (const int*)d_in[2];
    const float* textMask = (const float*)d_in[3];
    const float* audioMask = (const float*)d_in[4];
    const float* videoMask = (const float*)d_in[5];
    const float* W2 = (const float*)d_in[6];
    const float* a2 = (const float*)d_in[7];
    const float* Wl0 = (const float*)d_in[8];
    const float* Wr0 = (const float*)d_in[9];
    const float* a0 = (const float*)d_in[10];
    const float* Wres0 = (const float*)d_in[11];
    const float* b0 = (const float*)d_in[12];
    const float* Wl1 = (const float*)d_in[13];
    const float* Wr1 = (const float*)d_in[14];
    const float* a1 = (const float*)d_in[15];
    const float* Wres1 = (const float*)d_in[16];
    const float* b1 = (const float*)d_in[17];
    const float* Wlin = (const float*)d_in[18];
    const float* blin = (const float*)d_in[19];
    float* out = (float*)d_out;

    __half *p_hA, *p_WbigT, *p_WcatT, *p_x1A;
    float *p_big, *p_l1out, *p_lg0, *p_lg1, *p_lg2, *p_h3, *p_out1;
    cudaGetSymbolAddress((void**)&p_hA, g_hA);
    cudaGetSymbolAddress((void**)&p_WbigT, g_WbigT);
    cudaGetSymbolAddress((void**)&p_WcatT, g_WcatT);
    cudaGetSymbolAddress((void**)&p_big, g_big);
    cudaGetSymbolAddress((void**)&p_x1A, g_x1A);
    cudaGetSymbolAddress((void**)&p_l1out, g_l1out);
    cudaGetSymbolAddress((void**)&p_lg0, g_lg0);
    cudaGetSymbolAddress((void**)&p_lg1, g_lg1);
    cudaGetSymbolAddress((void**)&p_lg2, g_lg2);
    cudaGetSymbolAddress((void**)&p_h3, g_h3);
    cudaGetSymbolAddress((void**)&p_out1, g_out1);

    cudaFuncSetAttribute(fp16GemmKernel,
                         cudaFuncAttributeMaxDynamicSharedMemorySize, GEMM_SMEM);

    // preprocessing (+ packed fp16 A emit)
    zeroKernel<<<(NNODES + 255) / 256, 256>>>();
    {
        dim3 g((IN_DIM + 255) / 256, 40);
        colsumKernel<<<g, 256>>>(features);
    }
    preprocessKernel<<<MPAD, 256>>>(features, textMask, audioMask, videoMask);
    packWbigTKernel<<<(NCT0 * NKT0 * 4096 + 255) / 256, 256>>>(Wl0, Wr0, Wres0, W2);
    packWcatTKernel<<<(NKT1 * 4096 + 255) / 256, 256>>>(Wl1, Wr1, Wres1);

    // fused big GEMM: [10112 x 1280] x [1280 x 3200] -> g_big [10000 x 3104]
    {
        dim3 g(NRT, NCT0);
        fp16GemmKernel<<<g, 256, GEMM_SMEM>>>(p_hA, p_WbigT, NKT0, p_big, NBIG,
                                              NNODES, NBIG);
    }

    // CSR build
    histKernel<<<(NEDGES + 255) / 256, 256>>>(dst);
    scanKernel<<<1, 1024>>>();
    fillCsrKernel<<<(NEDGES + 255) / 256, 256>>>(dst);

    // gat_inner -> h3 (z2 = g_big cols 3072..3103)
    innerNodeTermsKernel<<<(NNODES * NH + 255) / 256, 256>>>(a2);
    innerEdgeLogitsKernel<<<(NEDGES * NH + 255) / 256, 256>>>(src, dst);
    segSoftmaxKernel<<<(NNODES * NH + 255) / 256, 256>>>(p_lg2);
    aggSmallKernel<<<(NNODES * 32 + 255) / 256, 256>>>(p_big + 3 * HD0, NBIG, p_lg2,
                                                       src, (const float*)0, 0,
                                                       (const float*)0, p_h3, 0);

    // gatv2 layer 0 -> x1 (packed fp16 tiles)
    gatv2EdgeLogits0Kernel<<<NEDGES, 128>>>(src, dst, a0);
    segSoftmaxKernel<<<(NNODES * NH + 255) / 256, 256>>>(p_lg0);
    gatv2Agg0Kernel<<<MPAD, 256>>>(src, b0);

    // layer-1 projections: [10112 x 1024] x [1024 x 128] -> g_l1out [10000 x 96]
    {
        dim3 g(NRT, 1);
        fp16GemmKernel<<<g, 256, GEMM_SMEM>>>(p_x1A, p_WcatT, NKT1, p_l1out, L1W,
                                              NNODES, L1W);
    }

    // gatv2 layer 1 -> out1
    gatv2EdgeLogits1Kernel<<<(NEDGES * 32 + 255) / 256, 256>>>(src, dst, a1);
    segSoftmaxKernel<<<(NNODES * NH + 255) / 256, 256>>>(p_lg1);
    aggSmallKernel<<<(NNODES * 32 + 255) / 256, 256>>>(p_l1out, L1W, p_lg1, src,
                                                       p_l1out + 2 * HD1, L1W, b1,
                                                       p_out1, 1);

    // final linear
    finalLinearKernel<<<(NNODES + 255) / 256, 256>>>(Wlin, blin, out);
}